// round 15
// baseline (speedup 1.0000x reference)
#include <cuda_runtime.h>
#include <cuda_fp16.h>
#include <cstdint>

#define NH   8
#define FD   128
#define DVD  16
#define LL   50
#define NT   256

// ---------------- smem layout (bytes) ----------------
#define OFF_SP   0                      // p_all [2][64][8] f32 (+c folded)
#define OFF_SR   4096                   // r_all [2][64][8] f32
#define OFF_XHI  8192                   // X hi [128][256B] swizzled fp16
#define OFF_XLO  (OFF_XHI + 32768)
#define OFF_AHI  (OFF_XLO + 32768)      // At hi (per head, prefetched)
#define OFF_ALO  (OFF_AHI + 32768)      // At lo
#define OFF_WHI  (OFF_ALO + 32768)      // Wvt hi [16][256B]
#define OFF_WLO  (OFF_WHI + 4096)
#define OFF_YHI  (OFF_WLO + 4096)       // Y hi [128][256B] swizzled
#define OFF_V    (OFF_YHI + 32768)      // V f32 [2][64][16]
#define OFF_P    (OFF_V + 8192)         // Ylo (GEMM phase) / P f32 [2][64][65]
#define SMEM_TOTAL (OFF_P + 2*64*65*4)  // 221696

// ------------- precomputed folded weights (fp16 hi/lo) -------------
__device__ __align__(16) __half g_Ahi[NH][128 * 128];
__device__ __align__(16) __half g_Alo[NH][128 * 128];
__device__ __align__(16) __half g_Whi[NH][16 * 128];
__device__ __align__(16) __half g_Wlo[NH][16 * 128];
__device__ float g_u[NH][FD];
__device__ float g_w[NH][FD];
__device__ float g_c[NH];

// swizzled byte offset in a [rows][128 f16] tile (256B rows, 16B-chunk XOR)
__host__ __device__ __forceinline__ uint32_t xoff(int r, int c) {
    return (uint32_t)r * 256u
         + (uint32_t)(((((c >> 3) ^ (r & 7))) << 4) + (c & 7) * 2);
}

// ---------------- PTX helpers ----------------
__device__ __forceinline__ uint32_t smem_u32(const void* p) {
    uint32_t a;
    asm("{ .reg .u64 t; cvta.to.shared.u64 t, %1; cvt.u32.u64 %0, t; }"
        : "=r"(a) : "l"(p));
    return a;
}
__device__ __forceinline__ void ldsm_x4(uint32_t a[4], uint32_t addr) {
    asm volatile("ldmatrix.sync.aligned.m8n8.x4.shared.b16 {%0,%1,%2,%3}, [%4];"
                 : "=r"(a[0]), "=r"(a[1]), "=r"(a[2]), "=r"(a[3]) : "r"(addr));
}
__device__ __forceinline__ void ldsm_x2(uint32_t a[2], uint32_t addr) {
    asm volatile("ldmatrix.sync.aligned.m8n8.x2.shared.b16 {%0,%1}, [%2];"
                 : "=r"(a[0]), "=r"(a[1]) : "r"(addr));
}
// main term: f16 x f16 -> f32 accum
__device__ __forceinline__ void mma_f32(float c[4], const uint32_t a[4],
                                        const uint32_t b0, const uint32_t b1) {
    asm volatile(
        "mma.sync.aligned.m16n8k16.row.col.f32.f16.f16.f32 "
        "{%0,%1,%2,%3}, {%4,%5,%6,%7}, {%8,%9}, {%0,%1,%2,%3};"
        : "+f"(c[0]), "+f"(c[1]), "+f"(c[2]), "+f"(c[3])
        : "r"(a[0]), "r"(a[1]), "r"(a[2]), "r"(a[3]), "r"(b0), "r"(b1));
}
// correction terms: f16 x f16 -> f16 accum (2x f32-accum rate)
__device__ __forceinline__ void mma_f16(uint32_t& d0, uint32_t& d1,
                                        const uint32_t a[4],
                                        const uint32_t b0, const uint32_t b1) {
    asm volatile(
        "mma.sync.aligned.m16n8k16.row.col.f16.f16.f16.f16 "
        "{%0,%1}, {%2,%3,%4,%5}, {%6,%7}, {%0,%1};"
        : "+r"(d0), "+r"(d1)
        : "r"(a[0]), "r"(a[1]), "r"(a[2]), "r"(a[3]), "r"(b0), "r"(b1));
}
__device__ __forceinline__ void fold_corr(float c[4], uint32_t d0, uint32_t d1) {
    float2 f0 = __half22float2(*(__half2*)&d0);
    float2 f1 = __half22float2(*(__half2*)&d1);
    c[0] += f0.x;  c[1] += f0.y;  c[2] += f1.x;  c[3] += f1.y;
}
#define CP_ASYNC16(s, g) \
    asm volatile("cp.async.cg.shared.global [%0], [%1], 16;" :: "r"(s), "l"(g))
#define CP_COMMIT() asm volatile("cp.async.commit_group;" ::: "memory")
#define CP_WAIT0()  asm volatile("cp.async.wait_group 0;" ::: "memory")

__device__ __forceinline__ uint32_t pack_f16(float a, float b) {
    __half2 t = __floats2half2_rn(a, b);
    return *(uint32_t*)&t;
}

// ---------------------------------------------------------------------------
// Kernel 1: fold A = Wq Wk^T (fp16 hi/lo, swizzled At), Wvt hi/lo, biases.
// grid (NH, 64): 1 output element per thread, 4-way ILP on the e-reduction.
// ---------------------------------------------------------------------------
__global__ void __launch_bounds__(NT)
precompute_kernel(const float* __restrict__ Wq,
                  const float* __restrict__ bq,
                  const float* __restrict__ Wk,
                  const float* __restrict__ bk,
                  const float* __restrict__ Wv) {
    const int h     = blockIdx.x;
    const int slice = blockIdx.y;
    const int tid   = threadIdx.x;
    const float* wq = Wq + h * FD * 128;
    const float* wk = Wk + h * FD * 128;

    {
        const int o  = slice * NT + tid;
        const int f  = o >> 7;
        const int fp = o & 127;
        const float4* qrow = (const float4*)(wq + f * 128);
        const float4* krow = (const float4*)(wk + fp * 128);
        float a0 = 0.f, a1 = 0.f, a2 = 0.f, a3 = 0.f;
        #pragma unroll
        for (int e4 = 0; e4 < 32; e4 += 4) {
            float4 q0 = qrow[e4],     k0 = krow[e4];
            float4 q1 = qrow[e4 + 1], k1 = krow[e4 + 1];
            float4 q2 = qrow[e4 + 2], k2 = krow[e4 + 2];
            float4 q3 = qrow[e4 + 3], k3 = krow[e4 + 3];
            a0 += q0.x * k0.x + q0.y * k0.y + q0.z * k0.z + q0.w * k0.w;
            a1 += q1.x * k1.x + q1.y * k1.y + q1.z * k1.z + q1.w * k1.w;
            a2 += q2.x * k2.x + q2.y * k2.y + q2.z * k2.z + q2.w * k2.w;
            a3 += q3.x * k3.x + q3.y * k3.y + q3.z * k3.z + q3.w * k3.w;
        }
        float acc = (a0 + a1) + (a2 + a3);
        __half hi = __float2half_rn(acc);
        float rem = acc - __half2float(hi);
        uint32_t off = xoff(fp, f);
        *(__half*)((char*)g_Ahi[h] + off) = hi;
        *(__half*)((char*)g_Alo[h] + off) = __float2half_rn(rem);
    }

    if (slice == 0) {
        #pragma unroll
        for (int it = 0; it < 8; it++) {
            int idx = it * NT + tid;
            int dv = idx >> 7, f = idx & 127;
            float v = Wv[h * FD * DVD + f * DVD + dv];
            __half hi = __float2half_rn(v);
            float rem = v - __half2float(hi);
            uint32_t off = xoff(dv, f);
            *(__half*)((char*)g_Whi[h] + off) = hi;
            *(__half*)((char*)g_Wlo[h] + off) = __float2half_rn(rem);
        }
    } else if (slice == 1) {
        if (tid < FD) {
            const float4* qrow = (const float4*)(wq + tid * 128);
            const float4* krow = (const float4*)(wk + tid * 128);
            const float4* bkv  = (const float4*)(bk + h * 128);
            const float4* bqv  = (const float4*)(bq + h * 128);
            float au = 0.f, aw = 0.f;
            #pragma unroll
            for (int e4 = 0; e4 < 32; e4++) {
                float4 q = qrow[e4], k = krow[e4];
                float4 bb = bkv[e4], bs = bqv[e4];
                au += q.x * bb.x + q.y * bb.y + q.z * bb.z + q.w * bb.w;
                aw += k.x * bs.x + k.y * bs.y + k.z * bs.z + k.w * bs.w;
            }
            g_u[h][tid] = au;
            g_w[h][tid] = aw;
        } else if (tid == 128) {
            const float4* bqv = (const float4*)(bq + h * 128);
            const float4* bkv = (const float4*)(bk + h * 128);
            float c = 0.f;
            #pragma unroll
            for (int e4 = 0; e4 < 32; e4++) {
                float4 a = bqv[e4], b = bkv[e4];
                c += a.x * b.x + a.y * b.y + a.z * b.z + a.w * b.w;
            }
            g_c[h] = c;
        }
    }
}

// ---------------------------------------------------------------------------
// Kernel 2: HMMA attention, 256 threads, 2 batches per CTA (M = 128 rows).
// Double-buffered k-loops: k+1's ldmatrix loads issued before k's MMAs.
// ---------------------------------------------------------------------------
__global__ void __launch_bounds__(NT, 1)
attn_mma_kernel(const float* __restrict__ hid,
                const float* __restrict__ bv,
                float* __restrict__ out) {
    extern __shared__ char smc[];
    const uint32_t sb = smem_u32(smc);
    const int tid  = threadIdx.x;
    const int wid  = tid >> 5;
    const int lane = tid & 31;
    const int bid  = blockIdx.x;

    float* spf = (float*)(smc + OFF_SP);
    float* srf = (float*)(smc + OFF_SR);
    float* sVf = (float*)(smc + OFF_V);
    float* sPf = (float*)(smc + OFF_P);

    // ---- load x (2 batches), fp16 hi/lo split, swizzled ----
    for (int i = tid; i < 128 * 64; i += NT) {
        int row = i >> 6;
        int cp  = (i & 63) * 2;
        int bb = row >> 6, l = row & 63;
        float v0 = 0.f, v1 = 0.f;
        if (l < LL) {
            const float* xr = hid + (long long)(2 * bid + bb) * (LL * FD) + l * FD + cp;
            v0 = xr[0]; v1 = xr[1];
        }
        __half h0 = __float2half_rn(v0), h1 = __float2half_rn(v1);
        float r0 = v0 - __half2float(h0), r1 = v1 - __half2float(h1);
        uint32_t off = xoff(row, cp);
        __half2 hw = __halves2half2(h0, h1);
        *(uint32_t*)(smc + OFF_XHI + off) = *(uint32_t*)&hw;
        *(uint32_t*)(smc + OFF_XLO + off) = pack_f16(r0, r1);
    }

    // ---- prologue: prefetch head 0 weights ----
    {
        const char* gh = (const char*)g_Ahi[0];
        const char* gl = (const char*)g_Alo[0];
        #pragma unroll
        for (int j = 0; j < 8; j++) {
            uint32_t o = (uint32_t)(j * 4096 + tid * 16);
            CP_ASYNC16(sb + OFF_AHI + o, gh + o);
            CP_ASYNC16(sb + OFF_ALO + o, gl + o);
        }
        CP_ASYNC16(sb + OFF_WHI + tid * 16, (const char*)g_Whi[0] + tid * 16);
        CP_ASYNC16(sb + OFF_WLO + tid * 16, (const char*)g_Wlo[0] + tid * 16);
        CP_COMMIT();
    }

    // ---- all-head p/r bias dots, once (overlaps prefetch) ----
    {
        int bb = tid >> 7;
        int l  = (tid >> 1) & 63;
        int pr = tid & 1;
        float acc[8];
        #pragma unroll
        for (int h2 = 0; h2 < 8; h2++) acc[h2] = 0.f;
        if (l < LL) {
            const float* xr = hid + (long long)(2 * bid + bb) * (LL * FD) + l * FD;
            const float* vb = pr ? &g_w[0][0] : &g_u[0][0];
            #pragma unroll 2
            for (int f = 0; f < FD; f += 4) {
                float4 xq = *(const float4*)(xr + f);
                #pragma unroll
                for (int h2 = 0; h2 < 8; h2++) {
                    const float* v = vb + h2 * FD + f;
                    acc[h2] += xq.x * v[0] + xq.y * v[1] + xq.z * v[2] + xq.w * v[3];
                }
            }
        }
        float* dst = pr ? srf : spf;
        #pragma unroll
        for (int h2 = 0; h2 < 8; h2++)
            dst[((bb << 6) + l) * 8 + h2] = acc[h2] + (pr ? 0.f : g_c[h2]);
    }

    // ---- ldmatrix lane-address components ----
    const int lr   = lane & 7;
    const int quad = lane >> 3;
    const int ahalf = quad >> 1;
    const int i15  = lane & 15;
    const int blr  = i15 & 7;
    const int bhalf = i15 >> 3;
    const uint32_t bRowOff = (uint32_t)blr * 256u;
    const uint32_t bPair   = (uint32_t)((lane >> 4) << 11);
    const int g  = lane >> 2;
    const int tg = lane & 3;

    const int ms = wid & 3;
    const int nh = wid >> 2;
    const uint32_t aRow1 = (uint32_t)(ms * 32 + lr + ((quad & 1) << 3)) * 256u;
    const uint32_t aRow2 = (uint32_t)(wid * 16 + lr + ((quad & 1) << 3)) * 256u;
    const int bb2 = wid >> 2;

    for (int h = 0; h < NH; h++) {
        CP_WAIT0();
        __syncthreads();                                   // ---- s1 ----

        // ======== GEMM1: Y = X·Atᵀ + V rider, 2 passes, k-pipelined ========
        #pragma unroll
        for (int pass = 0; pass < 2; pass++) {
            float cY[2][4][4];
            uint32_t cc[2][4][2];
            float cV[2][4];
            uint32_t cVc[2][2];
            #pragma unroll
            for (int mt = 0; mt < 2; mt++) {
                #pragma unroll
                for (int j = 0; j < 4; j++) {
                    #pragma unroll
                    for (int q = 0; q < 4; q++) cY[mt][j][q] = 0.f;
                    cc[mt][j][0] = 0u; cc[mt][j][1] = 0u;
                }
                #pragma unroll
                for (int q = 0; q < 4; q++) cV[mt][q] = 0.f;
                cVc[mt][0] = 0u; cVc[mt][1] = 0u;
            }

            uint32_t Ah0[2][4], Al0[2][4], Ah1[2][4], Al1[2][4];
            uint32_t Bh[2][2][4], Bl[2][2][4];
            uint32_t Wh[2][2], Wl[2][2];

#define G1_LOAD(kk, s) do {                                                    \
    uint32_t ca_ = (uint32_t)(((2 * (kk) + ahalf) ^ lr) << 4);                 \
    ldsm_x4(Ah0[s], sb + OFF_XHI + aRow1 + ca_);                               \
    ldsm_x4(Al0[s], sb + OFF_XLO + aRow1 + ca_);                               \
    ldsm_x4(Ah1[s], sb + OFF_XHI + aRow1 + 4096u + ca_);                       \
    ldsm_x4(Al1[s], sb + OFF_XLO + aRow1 + 4096u + ca_);                       \
    uint32_t cb_ = (uint32_t)(((2 * (kk) + bhalf) ^ blr) << 4);                \
    uint32_t bo_ = bRowOff + cb_ + bPair;                                      \
    uint32_t o0_ = bo_ + (uint32_t)((nh * 8 + pass * 4) * 2048);               \
    uint32_t o1_ = bo_ + (uint32_t)((nh * 8 + pass * 4 + 2) * 2048);           \
    ldsm_x4(Bh[s][0], sb + OFF_AHI + o0_);                                     \
    ldsm_x4(Bl[s][0], sb + OFF_ALO + o0_);                                     \
    ldsm_x4(Bh[s][1], sb + OFF_AHI + o1_);                                     \
    ldsm_x4(Bl[s][1], sb + OFF_ALO + o1_);                                     \
    if (pass == 0) {                                                           \
        uint32_t ow_ = bRowOff + cb_ + (uint32_t)(nh * 2048);                  \
        ldsm_x2(Wh[s], sb + OFF_WHI + ow_);                                    \
        ldsm_x2(Wl[s], sb + OFF_WLO + ow_);                                    \
    }                                                                          \
} while (0)

            G1_LOAD(0, 0);
            #pragma unroll
            for (int k = 0; k < 8; k++) {
                const int s = k & 1;
                if (k < 7) G1_LOAD(k + 1, s ^ 1);
                #pragma unroll
                for (int jp = 0; jp < 2; jp++) {
                    const int j0 = jp * 2, j1 = jp * 2 + 1;
                    mma_f32(cY[0][j0], Ah0[s], Bh[s][jp][0], Bh[s][jp][1]);
                    mma_f16(cc[0][j0][0], cc[0][j0][1], Ah0[s], Bl[s][jp][0], Bl[s][jp][1]);
                    mma_f16(cc[0][j0][0], cc[0][j0][1], Al0[s], Bh[s][jp][0], Bh[s][jp][1]);
                    mma_f32(cY[1][j0], Ah1[s], Bh[s][jp][0], Bh[s][jp][1]);
                    mma_f16(cc[1][j0][0], cc[1][j0][1], Ah1[s], Bl[s][jp][0], Bl[s][jp][1]);
                    mma_f16(cc[1][j0][0], cc[1][j0][1], Al1[s], Bh[s][jp][0], Bh[s][jp][1]);
                    mma_f32(cY[0][j1], Ah0[s], Bh[s][jp][2], Bh[s][jp][3]);
                    mma_f16(cc[0][j1][0], cc[0][j1][1], Ah0[s], Bl[s][jp][2], Bl[s][jp][3]);
                    mma_f16(cc[0][j1][0], cc[0][j1][1], Al0[s], Bh[s][jp][2], Bh[s][jp][3]);
                    mma_f32(cY[1][j1], Ah1[s], Bh[s][jp][2], Bh[s][jp][3]);
                    mma_f16(cc[1][j1][0], cc[1][j1][1], Ah1[s], Bl[s][jp][2], Bl[s][jp][3]);
                    mma_f16(cc[1][j1][0], cc[1][j1][1], Al1[s], Bh[s][jp][2], Bh[s][jp][3]);
                }
                if (pass == 0) {
                    mma_f32(cV[0], Ah0[s], Wh[s][0], Wh[s][1]);
                    mma_f16(cVc[0][0], cVc[0][1], Ah0[s], Wl[s][0], Wl[s][1]);
                    mma_f16(cVc[0][0], cVc[0][1], Al0[s], Wh[s][0], Wh[s][1]);
                    mma_f32(cV[1], Ah1[s], Wh[s][0], Wh[s][1]);
                    mma_f16(cVc[1][0], cVc[1][1], Ah1[s], Wl[s][0], Wl[s][1]);
                    mma_f16(cVc[1][0], cVc[1][1], Al1[s], Wh[s][0], Wh[s][1]);
                }
            }
#undef G1_LOAD

            // fold + write this pass's Y tiles (hi->YHI, lo->P) and V
            #pragma unroll
            for (int mt = 0; mt < 2; mt++) {
                const int rbase = ms * 32 + mt * 16;
                #pragma unroll
                for (int j = 0; j < 4; j++) {
                    fold_corr(cY[mt][j], cc[mt][j][0], cc[mt][j][1]);
                    int col = nh * 64 + (pass * 4 + j) * 8 + tg * 2;
                    uint32_t o0 = xoff(rbase + g, col);
                    uint32_t o1 = xoff(rbase + 8 + g, col);
                    float y0 = cY[mt][j][0], y1 = cY[mt][j][1];
                    float y2 = cY[mt][j][2], y3 = cY[mt][j][3];
                    __half h0 = __float2half_rn(y0), h1 = __float2half_rn(y1);
                    __half h2 = __float2half_rn(y2), h3 = __float2half_rn(y3);
                    __half2 w0 = __halves2half2(h0, h1);
                    __half2 w1 = __halves2half2(h2, h3);
                    *(uint32_t*)(smc + OFF_YHI + o0) = *(uint32_t*)&w0;
                    *(uint32_t*)(smc + OFF_YHI + o1) = *(uint32_t*)&w1;
                    *(uint32_t*)(smc + OFF_P + o0) =
                        pack_f16(y0 - __half2float(h0), y1 - __half2float(h1));
                    *(uint32_t*)(smc + OFF_P + o1) =
                        pack_f16(y2 - __half2float(h2), y3 - __half2float(h3));
                }
                if (pass == 0) {
                    fold_corr(cV[mt], cVc[mt][0], cVc[mt][1]);
                    const int dv = nh * 8 + tg * 2;
                    const int bb = rbase >> 6, ml = (rbase & 63) + g;
                    float b0 = bv[h * DVD + dv], b1 = bv[h * DVD + dv + 1];
                    float* v0 = sVf + (bb * 64 + ml) * 16 + dv;
                    float* v1 = sVf + (bb * 64 + ml + 8) * 16 + dv;
                    v0[0] = cV[mt][0] + b0;  v0[1] = cV[mt][1] + b1;
                    v1[0] = cV[mt][2] + b0;  v1[1] = cV[mt][3] + b1;
                }
            }
        }
        __syncthreads();                                   // ---- s2 ----

        // ======== prefetch next head's At/Wvt ========
        if (h + 1 < NH) {
            const char* gh = (const char*)g_Ahi[h + 1];
            const char* gl = (const char*)g_Alo[h + 1];
            #pragma unroll
            for (int j = 0; j < 8; j++) {
                uint32_t o = (uint32_t)(j * 4096 + tid * 16);
                CP_ASYNC16(sb + OFF_AHI + o, gh + o);
                CP_ASYNC16(sb + OFF_ALO + o, gl + o);
            }
            CP_ASYNC16(sb + OFF_WHI + tid * 16, (const char*)g_Whi[h + 1] + tid * 16);
            CP_ASYNC16(sb + OFF_WLO + tid * 16, (const char*)g_Wlo[h + 1] + tid * 16);
            CP_COMMIT();
        }

        // ======== GEMM2: C2[m,l] = X·Yᵀ, 7 n-tiles, k-pipelined ========
        float cS[7][4];
        uint32_t cSc[7][2];
        #pragma unroll
        for (int n = 0; n < 7; n++) {
            #pragma unroll
            for (int q = 0; q < 4; q++) cS[n][q] = 0.f;
            cSc[n][0] = 0u; cSc[n][1] = 0u;
        }
        {
            const uint32_t ybase = (uint32_t)(bb2 * 64 * 256);
            uint32_t A2h[2][4], A2l[2][4];
            uint32_t B2h[2][3][4], B2l[2][3][4];
            uint32_t B6h[2][2], B6l[2][2];

#define G2_LOAD(kk, s) do {                                                    \
    uint32_t ca_ = (uint32_t)(((2 * (kk) + ahalf) ^ lr) << 4);                 \
    ldsm_x4(A2h[s], sb + OFF_XHI + aRow2 + ca_);                               \
    ldsm_x4(A2l[s], sb + OFF_XLO + aRow2 + ca_);                               \
    uint32_t cb_ = (uint32_t)(((2 * (kk) + bhalf) ^ blr) << 4);                \
    uint32_t bo_ = ybase + bRowOff + cb_;                                      \
    ldsm_x4(B2h[s][0], sb + OFF_YHI + bo_ + bPair);                            \
    ldsm_x4(B2l[s][0], sb + OFF_P   + bo_ + bPair);                            \
    ldsm_x4(B2h[s][1], sb + OFF_YHI + bo_ + bPair + 4096u);                    \
    ldsm_x4(B2l[s][1], sb + OFF_P   + bo_ + bPair + 4096u);                    \
    ldsm_x4(B2h[s][2], sb + OFF_YHI + bo_ + bPair + 8192u);                    \
    ldsm_x4(B2l[s][2], sb + OFF_P   + bo_ + bPair + 8192u);                    \
    ldsm_x2(B6h[s], sb + OFF_YHI + bo_ + 12288u);                              \
    ldsm_x2(B6l[s], sb + OFF_P   + bo_ + 12288u);                              \
} while (0)

            G2_LOAD(0, 0);
            #pragma unroll
            for (int k = 0; k < 8; k++) {
                const int s = k & 1;
                if (k < 7) G2_LOAD(k + 1, s ^ 1);
                #pragma unroll
                for (int np = 0; np < 3; np++) {
                    const int n0 = np * 2, n1 = np * 2 + 1;
                    mma_f32(cS[n0], A2h[s], B2h[s][np][0], B2h[s][np][1]);
                    mma_f16(cSc[n0][0], cSc[n0][1], A2h[s], B2l[s][np][0], B2l[s][np][1]);
                    mma_f16(cSc[n0][0], cSc[n0][1], A2l[s], B2h[s][np][0], B2h[s][np][1]);
                    mma_f32(cS[n1], A2h[s], B2h[s][np][2], B2h[s][np][3]);
                    mma_f16(cSc[n1][0], cSc[n1][1], A2h[s], B2l[s][np][2], B2l[s][np][3]);
                    mma_f16(cSc[n1][0], cSc[n1][1], A2l[s], B2h[s][np][2], B2h[s][np][3]);
                }
                mma_f32(cS[6], A2h[s], B6h[s][0], B6h[s][1]);
                mma_f16(cSc[6][0], cSc[6][1], A2h[s], B6l[s][0], B6l[s][1]);
                mma_f16(cSc[6][0], cSc[6][1], A2l[s], B6h[s][0], B6h[s][1]);
            }
#undef G2_LOAD
        }
        #pragma unroll
        for (int n = 0; n < 7; n++) fold_corr(cS[n], cSc[n][0], cSc[n][1]);
        __syncthreads();                                   // ---- s3 ----

        // ======== bias + leaky + softmax over l, P -> smem ========
        {
            const int mbase = ((wid & 3) << 4) + g;
            #pragma unroll
            for (int pair = 0; pair < 2; pair++) {
                const int m = mbase + pair * 8;
                const float rm = srf[((bb2 << 6) + m) * 8 + h];
                float vals[14];
                float mx = -1e30f;
                #pragma unroll
                for (int n = 0; n < 7; n++) {
                    #pragma unroll
                    for (int j = 0; j < 2; j++) {
                        int l = n * 8 + tg * 2 + j;
                        float v = cS[n][pair * 2 + j]
                                + spf[((bb2 << 6) + l) * 8 + h] + rm;
                        v = v > 0.f ? v : 0.1f * v;
                        if (l >= LL) v = -1e30f;
                        vals[n * 2 + j] = v;
                        mx = fmaxf(mx, v);
                    }
                }
                mx = fmaxf(mx, __shfl_xor_sync(0xffffffffu, mx, 1));
                mx = fmaxf(mx, __shfl_xor_sync(0xffffffffu, mx, 2));
                float sum = 0.f;
                #pragma unroll
                for (int q = 0; q < 14; q++) {
                    float e = __expf(vals[q] - mx);
                    vals[q] = e;
                    sum += e;
                }
                sum += __shfl_xor_sync(0xffffffffu, sum, 1);
                sum += __shfl_xor_sync(0xffffffffu, sum, 2);
                float inv = 1.f / sum;
                float* prow = sPf + (bb2 * 64 + m) * 65;
                #pragma unroll
                for (int n = 0; n < 7; n++) {
                    prow[n * 8 + tg * 2]     = vals[n * 2] * inv;
                    prow[n * 8 + tg * 2 + 1] = vals[n * 2 + 1] * inv;
                }
            }
        }
        __syncthreads();                                   // ---- s4 ----

        // ======== out = relu(Pᵀ·V), store head slice ========
        #pragma unroll
        for (int it = 0; it < 2; it++) {
            int item = tid + it * NT;
            int b2 = item >> 8, l = (item >> 2) & 63, dv = (item & 3) * 4;
            if (l < LL) {
                float4 acc = make_float4(0.f, 0.f, 0.f, 0.f);
                const float* pcol = sPf + b2 * 64 * 65 + l;
                const float* vb   = sVf + b2 * 1024 + dv;
                #pragma unroll 10
                for (int m = 0; m < LL; m++) {
                    float p = pcol[m * 65];
                    float4 vv = *(const float4*)(vb + m * 16);
                    acc.x += p * vv.x;  acc.y += p * vv.y;
                    acc.z += p * vv.z;  acc.w += p * vv.w;
                }
                acc.x = fmaxf(acc.x, 0.f);  acc.y = fmaxf(acc.y, 0.f);
                acc.z = fmaxf(acc.z, 0.f);  acc.w = fmaxf(acc.w, 0.f);
                *(float4*)(out + (long long)(2 * bid + b2) * (LL * NH * DVD)
                               + l * (NH * DVD) + h * DVD + dv) = acc;
            }
        }
    }
}

// ---------------------------------------------------------------------------
extern "C" void kernel_launch(void* const* d_in, const int* in_sizes, int n_in,
                              void* d_out, int out_size) {
    const float* hid = (const float*)d_in[0];
    const float* Wq  = (const float*)d_in[1];
    const float* bq  = (const float*)d_in[2];
    const float* Wk  = (const float*)d_in[3];
    const float* bk  = (const float*)d_in[4];
    const float* Wv  = (const float*)d_in[5];
    const float* bv  = (const float*)d_in[6];
    float* out = (float*)d_out;

    const int nb = in_sizes[0] / (LL * FD);

    cudaFuncSetAttribute(attn_mma_kernel,
                         cudaFuncAttributeMaxDynamicSharedMemorySize, SMEM_TOTAL);

    precompute_kernel<<<dim3(NH, 64), NT>>>(Wq, bq, Wk, bk, Wv);
    attn_mma_kernel<<<nb / 2, NT, SMEM_TOTAL>>>(hid, bv, out);
}

// round 16
// speedup vs baseline: 1.2163x; 1.2163x over previous
#include <cuda_runtime.h>
#include <cuda_fp16.h>
#include <cstdint>

#define NH   8
#define FD   128
#define DVD  16
#define LL   50
#define NT   256

// ---------------- smem layout (bytes) ----------------
#define OFF_SP   0                      // p_all [2][64][8] f32 (+c folded)
#define OFF_SR   4096                   // r_all [2][64][8] f32
#define OFF_XHI  8192                   // X hi [128][256B] swizzled fp16
#define OFF_XLO  (OFF_XHI + 32768)
#define OFF_AHI  (OFF_XLO + 32768)      // At hi (per head, prefetched)
#define OFF_ALO  (OFF_AHI + 32768)      // At lo
#define OFF_WHI  (OFF_ALO + 32768)      // Wvt hi [16][256B]
#define OFF_WLO  (OFF_WHI + 4096)
#define OFF_YHI  (OFF_WLO + 4096)       // Y hi [128][256B] swizzled
#define OFF_YLO  (OFF_YHI + 32768)      // Y lo (GEMM phase) / P^T fp16 [2][64][128B]
#define OFF_VT   (OFF_YLO + 32768)      // V^T fp16 hi [2][16][128B], lo at +4096
#define SMEM_TOTAL (OFF_VT + 8192)      // 221184

// ------------- precomputed folded weights (fp16 hi/lo) -------------
__device__ __align__(16) __half g_Ahi[NH][128 * 128];
__device__ __align__(16) __half g_Alo[NH][128 * 128];
__device__ __align__(16) __half g_Whi[NH][16 * 128];
__device__ __align__(16) __half g_Wlo[NH][16 * 128];
__device__ float g_u[NH][FD];
__device__ float g_w[NH][FD];
__device__ float g_c[NH];

// swizzled byte offset in a [rows][128 f16] tile (256B rows, 16B-chunk XOR)
__host__ __device__ __forceinline__ uint32_t xoff(int r, int c) {
    return (uint32_t)r * 256u
         + (uint32_t)(((((c >> 3) ^ (r & 7))) << 4) + (c & 7) * 2);
}
// swizzled byte offset in a [rows][64 f16] tile (128B rows, 16B-chunk XOR)
__device__ __forceinline__ uint32_t xoff128(int r, int c) {
    return (uint32_t)r * 128u
         + (uint32_t)(((((c >> 3) ^ (r & 7))) << 4) + (c & 7) * 2);
}

// ---------------- PTX helpers ----------------
__device__ __forceinline__ uint32_t smem_u32(const void* p) {
    uint32_t a;
    asm("{ .reg .u64 t; cvta.to.shared.u64 t, %1; cvt.u32.u64 %0, t; }"
        : "=r"(a) : "l"(p));
    return a;
}
__device__ __forceinline__ void ldsm_x4(uint32_t a[4], uint32_t addr) {
    asm volatile("ldmatrix.sync.aligned.m8n8.x4.shared.b16 {%0,%1,%2,%3}, [%4];"
                 : "=r"(a[0]), "=r"(a[1]), "=r"(a[2]), "=r"(a[3]) : "r"(addr));
}
__device__ __forceinline__ void ldsm_x4t(uint32_t a[4], uint32_t addr) {
    asm volatile("ldmatrix.sync.aligned.m8n8.x4.trans.shared.b16 {%0,%1,%2,%3}, [%4];"
                 : "=r"(a[0]), "=r"(a[1]), "=r"(a[2]), "=r"(a[3]) : "r"(addr));
}
__device__ __forceinline__ void ldsm_x2(uint32_t a[2], uint32_t addr) {
    asm volatile("ldmatrix.sync.aligned.m8n8.x2.shared.b16 {%0,%1}, [%2];"
                 : "=r"(a[0]), "=r"(a[1]) : "r"(addr));
}
// main term: f16 x f16 -> f32 accum
__device__ __forceinline__ void mma_f32(float c[4], const uint32_t a[4],
                                        const uint32_t b0, const uint32_t b1) {
    asm volatile(
        "mma.sync.aligned.m16n8k16.row.col.f32.f16.f16.f32 "
        "{%0,%1,%2,%3}, {%4,%5,%6,%7}, {%8,%9}, {%0,%1,%2,%3};"
        : "+f"(c[0]), "+f"(c[1]), "+f"(c[2]), "+f"(c[3])
        : "r"(a[0]), "r"(a[1]), "r"(a[2]), "r"(a[3]), "r"(b0), "r"(b1));
}
// correction terms: f16 x f16 -> f16 accum (2x f32-accum rate)
__device__ __forceinline__ void mma_f16(uint32_t& d0, uint32_t& d1,
                                        const uint32_t a[4],
                                        const uint32_t b0, const uint32_t b1) {
    asm volatile(
        "mma.sync.aligned.m16n8k16.row.col.f16.f16.f16.f16 "
        "{%0,%1}, {%2,%3,%4,%5}, {%6,%7}, {%0,%1};"
        : "+r"(d0), "+r"(d1)
        : "r"(a[0]), "r"(a[1]), "r"(a[2]), "r"(a[3]), "r"(b0), "r"(b1));
}
__device__ __forceinline__ void fold_corr(float c[4], uint32_t d0, uint32_t d1) {
    float2 f0 = __half22float2(*(__half2*)&d0);
    float2 f1 = __half22float2(*(__half2*)&d1);
    c[0] += f0.x;  c[1] += f0.y;  c[2] += f1.x;  c[3] += f1.y;
}
#define CP_ASYNC16(s, g) \
    asm volatile("cp.async.cg.shared.global [%0], [%1], 16;" :: "r"(s), "l"(g))
#define CP_COMMIT() asm volatile("cp.async.commit_group;" ::: "memory")
#define CP_WAIT0()  asm volatile("cp.async.wait_group 0;" ::: "memory")

__device__ __forceinline__ uint32_t pack_f16(float a, float b) {
    __half2 t = __floats2half2_rn(a, b);
    return *(uint32_t*)&t;
}

// ---------------------------------------------------------------------------
// Kernel 1: fold A = Wq Wk^T (fp16 hi/lo, swizzled At), Wvt hi/lo, biases.
// grid (NH, 64): 1 output element per thread, 4-way ILP on the e-reduction.
// ---------------------------------------------------------------------------
__global__ void __launch_bounds__(NT)
precompute_kernel(const float* __restrict__ Wq,
                  const float* __restrict__ bq,
                  const float* __restrict__ Wk,
                  const float* __restrict__ bk,
                  const float* __restrict__ Wv) {
    const int h     = blockIdx.x;
    const int slice = blockIdx.y;
    const int tid   = threadIdx.x;
    const float* wq = Wq + h * FD * 128;
    const float* wk = Wk + h * FD * 128;

    {
        const int o  = slice * NT + tid;
        const int f  = o >> 7;
        const int fp = o & 127;
        const float4* qrow = (const float4*)(wq + f * 128);
        const float4* krow = (const float4*)(wk + fp * 128);
        float a0 = 0.f, a1 = 0.f, a2 = 0.f, a3 = 0.f;
        #pragma unroll
        for (int e4 = 0; e4 < 32; e4 += 4) {
            float4 q0 = qrow[e4],     k0 = krow[e4];
            float4 q1 = qrow[e4 + 1], k1 = krow[e4 + 1];
            float4 q2 = qrow[e4 + 2], k2 = krow[e4 + 2];
            float4 q3 = qrow[e4 + 3], k3 = krow[e4 + 3];
            a0 += q0.x * k0.x + q0.y * k0.y + q0.z * k0.z + q0.w * k0.w;
            a1 += q1.x * k1.x + q1.y * k1.y + q1.z * k1.z + q1.w * k1.w;
            a2 += q2.x * k2.x + q2.y * k2.y + q2.z * k2.z + q2.w * k2.w;
            a3 += q3.x * k3.x + q3.y * k3.y + q3.z * k3.z + q3.w * k3.w;
        }
        float acc = (a0 + a1) + (a2 + a3);
        __half hi = __float2half_rn(acc);
        float rem = acc - __half2float(hi);
        uint32_t off = xoff(fp, f);
        *(__half*)((char*)g_Ahi[h] + off) = hi;
        *(__half*)((char*)g_Alo[h] + off) = __float2half_rn(rem);
    }

    if (slice == 0) {
        #pragma unroll
        for (int it = 0; it < 8; it++) {
            int idx = it * NT + tid;
            int dv = idx >> 7, f = idx & 127;
            float v = Wv[h * FD * DVD + f * DVD + dv];
            __half hi = __float2half_rn(v);
            float rem = v - __half2float(hi);
            uint32_t off = xoff(dv, f);
            *(__half*)((char*)g_Whi[h] + off) = hi;
            *(__half*)((char*)g_Wlo[h] + off) = __float2half_rn(rem);
        }
    } else if (slice == 1) {
        if (tid < FD) {
            const float4* qrow = (const float4*)(wq + tid * 128);
            const float4* krow = (const float4*)(wk + tid * 128);
            const float4* bkv  = (const float4*)(bk + h * 128);
            const float4* bqv  = (const float4*)(bq + h * 128);
            float au = 0.f, aw = 0.f;
            #pragma unroll
            for (int e4 = 0; e4 < 32; e4++) {
                float4 q = qrow[e4], k = krow[e4];
                float4 bb = bkv[e4], bs = bqv[e4];
                au += q.x * bb.x + q.y * bb.y + q.z * bb.z + q.w * bb.w;
                aw += k.x * bs.x + k.y * bs.y + k.z * bs.z + k.w * bs.w;
            }
            g_u[h][tid] = au;
            g_w[h][tid] = aw;
        } else if (tid == 128) {
            const float4* bqv = (const float4*)(bq + h * 128);
            const float4* bkv = (const float4*)(bk + h * 128);
            float c = 0.f;
            #pragma unroll
            for (int e4 = 0; e4 < 32; e4++) {
                float4 a = bqv[e4], b = bkv[e4];
                c += a.x * b.x + a.y * b.y + a.z * b.z + a.w * b.w;
            }
            g_c[h] = c;
        }
    }
}

// ---------------------------------------------------------------------------
// Kernel 2: HMMA attention, 256 threads, 2 batches per CTA (M = 128 rows).
// GEMM1/GEMM2 as R12/R14; PV epilogue now runs on tensor cores:
//   P^T stored fp16 (rows m, cols l, swizzled 128B rows) -> ldmatrix.x4.trans
//   V^T stored fp16 hi/lo (rows dv, cols m)              -> ldmatrix.x4
// ---------------------------------------------------------------------------
__global__ void __launch_bounds__(NT, 1)
attn_mma_kernel(const float* __restrict__ hid,
                const float* __restrict__ bv,
                float* __restrict__ out) {
    extern __shared__ char smc[];
    const uint32_t sb = smem_u32(smc);
    const int tid  = threadIdx.x;
    const int wid  = tid >> 5;
    const int lane = tid & 31;
    const int bid  = blockIdx.x;

    float* spf = (float*)(smc + OFF_SP);
    float* srf = (float*)(smc + OFF_SR);

    // ---- load x (2 batches), fp16 hi/lo split, swizzled ----
    for (int i = tid; i < 128 * 64; i += NT) {
        int row = i >> 6;
        int cp  = (i & 63) * 2;
        int bb = row >> 6, l = row & 63;
        float v0 = 0.f, v1 = 0.f;
        if (l < LL) {
            const float* xr = hid + (long long)(2 * bid + bb) * (LL * FD) + l * FD + cp;
            v0 = xr[0]; v1 = xr[1];
        }
        __half h0 = __float2half_rn(v0), h1 = __float2half_rn(v1);
        float r0 = v0 - __half2float(h0), r1 = v1 - __half2float(h1);
        uint32_t off = xoff(row, cp);
        __half2 hw = __halves2half2(h0, h1);
        *(uint32_t*)(smc + OFF_XHI + off) = *(uint32_t*)&hw;
        *(uint32_t*)(smc + OFF_XLO + off) = pack_f16(r0, r1);
    }

    // ---- prologue: prefetch head 0 weights ----
    {
        const char* gh = (const char*)g_Ahi[0];
        const char* gl = (const char*)g_Alo[0];
        #pragma unroll
        for (int j = 0; j < 8; j++) {
            uint32_t o = (uint32_t)(j * 4096 + tid * 16);
            CP_ASYNC16(sb + OFF_AHI + o, gh + o);
            CP_ASYNC16(sb + OFF_ALO + o, gl + o);
        }
        CP_ASYNC16(sb + OFF_WHI + tid * 16, (const char*)g_Whi[0] + tid * 16);
        CP_ASYNC16(sb + OFF_WLO + tid * 16, (const char*)g_Wlo[0] + tid * 16);
        CP_COMMIT();
    }

    // ---- all-head p/r bias dots, once (overlaps prefetch) ----
    {
        int bb = tid >> 7;
        int l  = (tid >> 1) & 63;
        int pr = tid & 1;
        float acc[8];
        #pragma unroll
        for (int h2 = 0; h2 < 8; h2++) acc[h2] = 0.f;
        if (l < LL) {
            const float* xr = hid + (long long)(2 * bid + bb) * (LL * FD) + l * FD;
            const float* vb = pr ? &g_w[0][0] : &g_u[0][0];
            #pragma unroll 2
            for (int f = 0; f < FD; f += 4) {
                float4 xq = *(const float4*)(xr + f);
                #pragma unroll
                for (int h2 = 0; h2 < 8; h2++) {
                    const float* v = vb + h2 * FD + f;
                    acc[h2] += xq.x * v[0] + xq.y * v[1] + xq.z * v[2] + xq.w * v[3];
                }
            }
        }
        float* dst = pr ? srf : spf;
        #pragma unroll
        for (int h2 = 0; h2 < 8; h2++)
            dst[((bb << 6) + l) * 8 + h2] = acc[h2] + (pr ? 0.f : g_c[h2]);
    }

    // ---- ldmatrix lane-address components ----
    const int lr   = lane & 7;
    const int quad = lane >> 3;
    const int ahalf = quad >> 1;
    const int i15  = lane & 15;
    const int blr  = i15 & 7;
    const int bhalf = i15 >> 3;
    const uint32_t bRowOff = (uint32_t)blr * 256u;
    const uint32_t bPair   = (uint32_t)((lane >> 4) << 11);
    const int g  = lane >> 2;
    const int tg = lane & 3;

    const int ms = wid & 3;
    const int nh = wid >> 2;
    const uint32_t aRow1 = (uint32_t)(ms * 32 + lr + ((quad & 1) << 3)) * 256u;
    const uint32_t aRow2 = (uint32_t)(wid * 16 + lr + ((quad & 1) << 3)) * 256u;
    const int bb2 = wid >> 2;

    // PV lane constants: A = P^T via ldmatrix.trans, B = V^T via ldmatrix
    const int pvRowK = (lane & 7) + ((lane >> 4) << 3);   // k(m) row within chunk
    const int pvLch  = (lane >> 3) & 1;                   // l chunk select
    const uint32_t vtRow   = (uint32_t)blr * 128u;
    const uint32_t vtPair  = (uint32_t)((lane >> 4) << 10);  // +8 dv rows

    for (int h = 0; h < NH; h++) {
        CP_WAIT0();
        __syncthreads();                                   // ---- s1 ----

        // ======== GEMM1: Y = X·Atᵀ + V rider, 2 passes of 4 tiles ========
        #pragma unroll
        for (int pass = 0; pass < 2; pass++) {
            float cY[2][4][4];
            uint32_t cc[2][4][2];
            float cV[2][4];
            uint32_t cVc[2][2];
            #pragma unroll
            for (int mt = 0; mt < 2; mt++) {
                #pragma unroll
                for (int j = 0; j < 4; j++) {
                    #pragma unroll
                    for (int q = 0; q < 4; q++) cY[mt][j][q] = 0.f;
                    cc[mt][j][0] = 0u; cc[mt][j][1] = 0u;
                }
                #pragma unroll
                for (int q = 0; q < 4; q++) cV[mt][q] = 0.f;
                cVc[mt][0] = 0u; cVc[mt][1] = 0u;
            }

            #pragma unroll
            for (int k = 0; k < 8; k++) {
                uint32_t ca = (uint32_t)(((2 * k + ahalf) ^ lr) << 4);
                uint32_t ahi0[4], alo0[4], ahi1[4], alo1[4];
                ldsm_x4(ahi0, sb + OFF_XHI + aRow1 + ca);
                ldsm_x4(alo0, sb + OFF_XLO + aRow1 + ca);
                ldsm_x4(ahi1, sb + OFF_XHI + aRow1 + 4096u + ca);
                ldsm_x4(alo1, sb + OFF_XLO + aRow1 + 4096u + ca);
                uint32_t cb = (uint32_t)(((2 * k + bhalf) ^ blr) << 4);
                uint32_t bo = bRowOff + cb + bPair;
                #pragma unroll
                for (int jp = 0; jp < 2; jp++) {
                    uint32_t o = bo + (uint32_t)((nh * 8 + pass * 4 + jp * 2) * 2048);
                    uint32_t bh[4], bl[4];
                    ldsm_x4(bh, sb + OFF_AHI + o);
                    ldsm_x4(bl, sb + OFF_ALO + o);
                    const int j0 = jp * 2, j1 = jp * 2 + 1;
                    mma_f32(cY[0][j0], ahi0, bh[0], bh[1]);
                    mma_f16(cc[0][j0][0], cc[0][j0][1], ahi0, bl[0], bl[1]);
                    mma_f16(cc[0][j0][0], cc[0][j0][1], alo0, bh[0], bh[1]);
                    mma_f32(cY[1][j0], ahi1, bh[0], bh[1]);
                    mma_f16(cc[1][j0][0], cc[1][j0][1], ahi1, bl[0], bl[1]);
                    mma_f16(cc[1][j0][0], cc[1][j0][1], alo1, bh[0], bh[1]);
                    mma_f32(cY[0][j1], ahi0, bh[2], bh[3]);
                    mma_f16(cc[0][j1][0], cc[0][j1][1], ahi0, bl[2], bl[3]);
                    mma_f16(cc[0][j1][0], cc[0][j1][1], alo0, bh[2], bh[3]);
                    mma_f32(cY[1][j1], ahi1, bh[2], bh[3]);
                    mma_f16(cc[1][j1][0], cc[1][j1][1], ahi1, bl[2], bl[3]);
                    mma_f16(cc[1][j1][0], cc[1][j1][1], alo1, bh[2], bh[3]);
                }
                if (pass == 0) {
                    uint32_t o = bRowOff + cb + (uint32_t)(nh * 2048);
                    uint32_t bh[2], bl[2];
                    ldsm_x2(bh, sb + OFF_WHI + o);
                    ldsm_x2(bl, sb + OFF_WLO + o);
                    mma_f32(cV[0], ahi0, bh[0], bh[1]);
                    mma_f16(cVc[0][0], cVc[0][1], ahi0, bl[0], bl[1]);
                    mma_f16(cVc[0][0], cVc[0][1], alo0, bh[0], bh[1]);
                    mma_f32(cV[1], ahi1, bh[0], bh[1]);
                    mma_f16(cVc[1][0], cVc[1][1], ahi1, bl[0], bl[1]);
                    mma_f16(cVc[1][0], cVc[1][1], alo1, bh[0], bh[1]);
                }
            }

            // fold + write this pass's Y tiles (hi->YHI, lo->YLO); V -> V^T f16
            #pragma unroll
            for (int mt = 0; mt < 2; mt++) {
                const int rbase = ms * 32 + mt * 16;
                #pragma unroll
                for (int j = 0; j < 4; j++) {
                    fold_corr(cY[mt][j], cc[mt][j][0], cc[mt][j][1]);
                    int col = nh * 64 + (pass * 4 + j) * 8 + tg * 2;
                    uint32_t o0 = xoff(rbase + g, col);
                    uint32_t o1 = xoff(rbase + 8 + g, col);
                    float y0 = cY[mt][j][0], y1 = cY[mt][j][1];
                    float y2 = cY[mt][j][2], y3 = cY[mt][j][3];
                    __half h0 = __float2half_rn(y0), h1 = __float2half_rn(y1);
                    __half h2 = __float2half_rn(y2), h3 = __float2half_rn(y3);
                    __half2 w0 = __halves2half2(h0, h1);
                    __half2 w1 = __halves2half2(h2, h3);
                    *(uint32_t*)(smc + OFF_YHI + o0) = *(uint32_t*)&w0;
                    *(uint32_t*)(smc + OFF_YHI + o1) = *(uint32_t*)&w1;
                    *(uint32_t*)(smc + OFF_YLO + o0) =
                        pack_f16(y0 - __half2float(h0), y1 - __half2float(h1));
                    *(uint32_t*)(smc + OFF_YLO + o1) =
                        pack_f16(y2 - __half2float(h2), y3 - __half2float(h3));
                }
                if (pass == 0) {
                    fold_corr(cV[mt], cVc[mt][0], cVc[mt][1]);
                    const int dv = nh * 8 + tg * 2;
                    const int bb = rbase >> 6, ml = (rbase & 63) + g;
                    float b0 = bv[h * DVD + dv], b1 = bv[h * DVD + dv + 1];
                    float v0 = cV[mt][0] + b0, v1 = cV[mt][1] + b1;
                    float v2 = cV[mt][2] + b0, v3 = cV[mt][3] + b1;
                    char* vh = smc + OFF_VT + bb * 2048;
                    char* vl = vh + 4096;
                    __half h0 = __float2half_rn(v0), h1 = __float2half_rn(v1);
                    __half h2 = __float2half_rn(v2), h3 = __float2half_rn(v3);
                    uint32_t q0 = xoff128(dv, ml),     q1 = xoff128(dv + 1, ml);
                    uint32_t q2 = xoff128(dv, ml + 8), q3 = xoff128(dv + 1, ml + 8);
                    *(__half*)(vh + q0) = h0;  *(__half*)(vh + q1) = h1;
                    *(__half*)(vh + q2) = h2;  *(__half*)(vh + q3) = h3;
                    *(__half*)(vl + q0) = __float2half_rn(v0 - __half2float(h0));
                    *(__half*)(vl + q1) = __float2half_rn(v1 - __half2float(h1));
                    *(__half*)(vl + q2) = __float2half_rn(v2 - __half2float(h2));
                    *(__half*)(vl + q3) = __float2half_rn(v3 - __half2float(h3));
                }
            }
        }
        __syncthreads();                                   // ---- s2 ----

        // ======== prefetch next head's At/Wvt ========
        if (h + 1 < NH) {
            const char* gh = (const char*)g_Ahi[h + 1];
            const char* gl = (const char*)g_Alo[h + 1];
            #pragma unroll
            for (int j = 0; j < 8; j++) {
                uint32_t o = (uint32_t)(j * 4096 + tid * 16);
                CP_ASYNC16(sb + OFF_AHI + o, gh + o);
                CP_ASYNC16(sb + OFF_ALO + o, gl + o);
            }
            CP_ASYNC16(sb + OFF_WHI + tid * 16, (const char*)g_Whi[h + 1] + tid * 16);
            CP_ASYNC16(sb + OFF_WLO + tid * 16, (const char*)g_Wlo[h + 1] + tid * 16);
            CP_COMMIT();
        }

        // ======== GEMM2: C2[m,l] = X·Yᵀ, 7 n-tiles (tile 7 fully masked) ====
        float cS[7][4];
        uint32_t cSc[7][2];
        #pragma unroll
        for (int n = 0; n < 7; n++) {
            #pragma unroll
            for (int q = 0; q < 4; q++) cS[n][q] = 0.f;
            cSc[n][0] = 0u; cSc[n][1] = 0u;
        }
        const uint32_t ybase = (uint32_t)(bb2 * 64 * 256);
        #pragma unroll
        for (int k = 0; k < 8; k++) {
            uint32_t ca = (uint32_t)(((2 * k + ahalf) ^ lr) << 4);
            uint32_t ahi[4], alo[4];
            ldsm_x4(ahi, sb + OFF_XHI + aRow2 + ca);
            ldsm_x4(alo, sb + OFF_XLO + aRow2 + ca);
            uint32_t cb = (uint32_t)(((2 * k + bhalf) ^ blr) << 4);
            uint32_t bo = ybase + bRowOff + cb;
            #pragma unroll
            for (int np = 0; np < 3; np++) {
                uint32_t o = bo + bPair + (uint32_t)(np * 2 * 2048);
                uint32_t bh[4], bl[4];
                ldsm_x4(bh, sb + OFF_YHI + o);
                ldsm_x4(bl, sb + OFF_YLO + o);
                const int n0 = np * 2, n1 = np * 2 + 1;
                mma_f32(cS[n0], ahi, bh[0], bh[1]);
                mma_f16(cSc[n0][0], cSc[n0][1], ahi, bl[0], bl[1]);
                mma_f16(cSc[n0][0], cSc[n0][1], alo, bh[0], bh[1]);
                mma_f32(cS[n1], ahi, bh[2], bh[3]);
                mma_f16(cSc[n1][0], cSc[n1][1], ahi, bl[2], bl[3]);
                mma_f16(cSc[n1][0], cSc[n1][1], alo, bh[2], bh[3]);
            }
            {
                uint32_t o = bo + (uint32_t)(6 * 2048);
                uint32_t bh[2], bl[2];
                ldsm_x2(bh, sb + OFF_YHI + o);
                ldsm_x2(bl, sb + OFF_YLO + o);
                mma_f32(cS[6], ahi, bh[0], bh[1]);
                mma_f16(cSc[6][0], cSc[6][1], ahi, bl[0], bl[1]);
                mma_f16(cSc[6][0], cSc[6][1], alo, bh[0], bh[1]);
            }
        }
        #pragma unroll
        for (int n = 0; n < 7; n++) fold_corr(cS[n], cSc[n][0], cSc[n][1]);
        __syncthreads();                                   // ---- s3 ----

        // ======== bias + leaky + softmax over l; P^T fp16 -> YLO region ====
        {
            char* ptb = smc + OFF_YLO + bb2 * 8192;
            const int mbase = ((wid & 3) << 4) + g;
            #pragma unroll
            for (int pair = 0; pair < 2; pair++) {
                const int m = mbase + pair * 8;
                const float rm = srf[((bb2 << 6) + m) * 8 + h];
                float vals[14];
                float mx = -1e30f;
                #pragma unroll
                for (int n = 0; n < 7; n++) {
                    #pragma unroll
                    for (int j = 0; j < 2; j++) {
                        int l = n * 8 + tg * 2 + j;
                        float v = cS[n][pair * 2 + j]
                                + spf[((bb2 << 6) + l) * 8 + h] + rm;
                        v = v > 0.f ? v : 0.1f * v;
                        if (l >= LL) v = -1e30f;
                        vals[n * 2 + j] = v;
                        mx = fmaxf(mx, v);
                    }
                }
                mx = fmaxf(mx, __shfl_xor_sync(0xffffffffu, mx, 1));
                mx = fmaxf(mx, __shfl_xor_sync(0xffffffffu, mx, 2));
                float sum = 0.f;
                #pragma unroll
                for (int q = 0; q < 14; q++) {
                    float e = __expf(vals[q] - mx);
                    vals[q] = e;
                    sum += e;
                }
                sum += __shfl_xor_sync(0xffffffffu, sum, 1);
                sum += __shfl_xor_sync(0xffffffffu, sum, 2);
                float inv = (m < LL) ? (1.f / sum) : 0.f;
                // P^T[m][l] fp16, swizzled 128B rows; zero l-chunk 7
                uint32_t rbyte = (uint32_t)m * 128u;
                uint32_t sw = (uint32_t)(m & 7);
                #pragma unroll
                for (int n = 0; n < 7; n++) {
                    uint32_t o = rbyte + (((uint32_t)n ^ sw) << 4) + (uint32_t)tg * 4;
                    *(uint32_t*)(ptb + o) =
                        pack_f16(vals[n * 2] * inv, vals[n * 2 + 1] * inv);
                }
                *(uint32_t*)(ptb + rbyte + ((7u ^ sw) << 4) + (uint32_t)tg * 4) = 0u;
            }
        }
        __syncthreads();                                   // ---- s4 ----

        // ======== PV via HMMA: out = relu(P·V) ========
        {
            // warp: batch bb2, l-slice (wid & 3)
            const int lslice = wid & 3;
            const uint32_t ptbase = sb + OFF_YLO + (uint32_t)(bb2 * 8192);
            const uint32_t vtbase = sb + OFF_VT + (uint32_t)(bb2 * 2048);
            float cO[2][4];
            #pragma unroll
            for (int nt = 0; nt < 2; nt++)
                #pragma unroll
                for (int q = 0; q < 4; q++) cO[nt][q] = 0.f;

            #pragma unroll
            for (int kk = 0; kk < 4; kk++) {
                // A: P^T (col-major A) via ldmatrix.trans
                const int rowk = kk * 16 + pvRowK;
                uint32_t aAddr = ptbase + (uint32_t)rowk * 128u
                    + ((uint32_t)((lslice * 2 + pvLch) ^ (rowk & 7)) << 4);
                uint32_t aP[4];
                ldsm_x4t(aP, aAddr);
                // B: V^T hi/lo, 2 n-tiles via pair trick
                uint32_t cbv = (uint32_t)(((2 * kk + bhalf) ^ blr) << 4);
                uint32_t bh[4], bl[4];
                ldsm_x4(bh, vtbase + vtRow + vtPair + cbv);
                ldsm_x4(bl, vtbase + 4096u + vtRow + vtPair + cbv);
                mma_f32(cO[0], aP, bh[0], bh[1]);
                mma_f32(cO[0], aP, bl[0], bl[1]);
                mma_f32(cO[1], aP, bh[2], bh[3]);
                mma_f32(cO[1], aP, bl[2], bl[3]);
            }

            // store out[l][h*16+dv], relu
            const long long obase = (long long)(2 * bid + bb2) * (LL * NH * DVD);
            const int l0 = lslice * 16 + g;
            #pragma unroll
            for (int nt = 0; nt < 2; nt++) {
                const int dv = nt * 8 + tg * 2;
                if (l0 < LL) {
                    float2 v = make_float2(fmaxf(cO[nt][0], 0.f),
                                           fmaxf(cO[nt][1], 0.f));
                    *(float2*)(out + obase + l0 * (NH * DVD) + h * DVD + dv) = v;
                }
                if (l0 + 8 < LL) {
                    float2 v = make_float2(fmaxf(cO[nt][2], 0.f),
                                           fmaxf(cO[nt][3], 0.f));
                    *(float2*)(out + obase + (l0 + 8) * (NH * DVD) + h * DVD + dv) = v;
                }
            }
        }
    }
}

// ---------------------------------------------------------------------------
extern "C" void kernel_launch(void* const* d_in, const int* in_sizes, int n_in,
                              void* d_out, int out_size) {
    const float* hid = (const float*)d_in[0];
    const float* Wq  = (const float*)d_in[1];
    const float* bq  = (const float*)d_in[2];
    const float* Wk  = (const float*)d_in[3];
    const float* bk  = (const float*)d_in[4];
    const float* Wv  = (const float*)d_in[5];
    const float* bv  = (const float*)d_in[6];
    float* out = (float*)d_out;

    const int nb = in_sizes[0] / (LL * FD);

    cudaFuncSetAttribute(attn_mma_kernel,
                         cudaFuncAttributeMaxDynamicSharedMemorySize, SMEM_TOTAL);

    precompute_kernel<<<dim3(NH, 64), NT>>>(Wq, bq, Wk, bk, Wv);
    attn_mma_kernel<<<nb / 2, NT, SMEM_TOTAL>>>(hid, bv, out);
}